// round 2
// baseline (speedup 1.0000x reference)
#include <cuda_runtime.h>
#include <math.h>

#define NMAX     50000
#define EMAX     850000
#define HC       384
#define CH       128
#define NHEAD    3

// ---------------- scratch (device globals; no allocation allowed) ----------
__device__ float    g_p[(size_t)NMAX * HC];     // projected features (per layer)
__device__ float    g_agg[(size_t)NMAX * HC];   // aggregated output (per layer)
__device__ float    g_asrc[NMAX * NHEAD];
__device__ float    g_adst[NMAX * NHEAD];
__device__ unsigned g_amax[NMAX * NHEAD];
__device__ float    g_denom[NMAX * NHEAD];
__device__ float    g_ex[(size_t)EMAX * NHEAD]; // alpha, later exp(alpha-max)
__device__ int      g_counts[NMAX];
__device__ int      g_rowoff[NMAX + 1];
__device__ int      g_cursor[NMAX];
__device__ int      g_csr_e[EMAX];
__device__ int      g_csr_s[EMAX];
__device__ int      g_is64;                     // 1 if edge_index is int64

// ---------------- helpers ---------------------------------------------------
__device__ __forceinline__ unsigned f2enc(float x) {
    unsigned b = __float_as_uint(x);
    return (b & 0x80000000u) ? ~b : (b | 0x80000000u);
}
__device__ __forceinline__ float enc2f(unsigned e) {
    return __uint_as_float((e & 0x80000000u) ? (e & 0x7fffffffu) : ~e);
}
__device__ __forceinline__ int load_idx(const void* ei, size_t i) {
    if (g_is64) return (int)((const long long*)ei)[i];
    return ((const int*)ei)[i];
}

// Detect edge_index dtype: view as int32; if int64 (LE, values < 2^31) every
// odd word is the zero high-half. 256 samples -> false positive prob ~0.
__global__ void detect_dtype_kernel(const int* __restrict__ ei32)
{
    __shared__ int any_nz;
    if (threadIdx.x == 0) any_nz = 0;
    __syncthreads();
    if (ei32[2 * threadIdx.x + 1] != 0) atomicOr(&any_nz, 1);
    __syncthreads();
    if (threadIdx.x == 0) g_is64 = any_nz ? 0 : 1;
}

// ---------------- SGEMM: C[M,N] = op(A)[M,K] @ B[K,N] (+bias) --------------
// 128x128 tile, BK=8, 256 threads, 8x8 per-thread microtile, fp32
template<int RELU_A>
__global__ __launch_bounds__(256) void sgemm_kernel(
    const float* __restrict__ A, const float* __restrict__ B,
    const float* __restrict__ bias, float* __restrict__ C,
    int M, int N, int K)
{
    __shared__ float As[8][128];
    __shared__ float Bs[8][128];
    const int tid = threadIdx.x;
    const int bm = blockIdx.y * 128;
    const int bn = blockIdx.x * 128;
    const int tx = tid & 15;
    const int ty = tid >> 4;
    const int arow = tid >> 1;
    const int acol = (tid & 1) << 2;
    const int brow = tid >> 5;
    const int bcol = (tid & 31) << 2;

    float acc[8][8];
#pragma unroll
    for (int i = 0; i < 8; i++)
#pragma unroll
        for (int j = 0; j < 8; j++) acc[i][j] = 0.f;

    const int gm = bm + arow;
    const bool avalid = (gm < M);

    for (int k0 = 0; k0 < K; k0 += 8) {
        float4 av = make_float4(0.f, 0.f, 0.f, 0.f);
        if (avalid)
            av = *reinterpret_cast<const float4*>(A + (size_t)gm * K + k0 + acol);
        if (RELU_A) {
            av.x = fmaxf(av.x, 0.f); av.y = fmaxf(av.y, 0.f);
            av.z = fmaxf(av.z, 0.f); av.w = fmaxf(av.w, 0.f);
        }
        float4 bv = make_float4(0.f, 0.f, 0.f, 0.f);
        const int gn = bn + bcol;
        const float* Brow = B + (size_t)(k0 + brow) * N;
        if (gn + 3 < N) {
            bv = *reinterpret_cast<const float4*>(Brow + gn);
        } else {
            if (gn     < N) bv.x = Brow[gn];
            if (gn + 1 < N) bv.y = Brow[gn + 1];
            if (gn + 2 < N) bv.z = Brow[gn + 2];
        }
        As[acol + 0][arow] = av.x;
        As[acol + 1][arow] = av.y;
        As[acol + 2][arow] = av.z;
        As[acol + 3][arow] = av.w;
        *reinterpret_cast<float4*>(&Bs[brow][bcol]) = bv;
        __syncthreads();

#pragma unroll
        for (int k = 0; k < 8; k++) {
            float4 a0 = *reinterpret_cast<const float4*>(&As[k][ty * 8]);
            float4 a1 = *reinterpret_cast<const float4*>(&As[k][ty * 8 + 4]);
            float4 b0 = *reinterpret_cast<const float4*>(&Bs[k][tx * 8]);
            float4 b1 = *reinterpret_cast<const float4*>(&Bs[k][tx * 8 + 4]);
            float a[8] = {a0.x, a0.y, a0.z, a0.w, a1.x, a1.y, a1.z, a1.w};
            float b[8] = {b0.x, b0.y, b0.z, b0.w, b1.x, b1.y, b1.z, b1.w};
#pragma unroll
            for (int i = 0; i < 8; i++)
#pragma unroll
                for (int j = 0; j < 8; j++)
                    acc[i][j] = fmaf(a[i], b[j], acc[i][j]);
        }
        __syncthreads();
    }

#pragma unroll
    for (int i = 0; i < 8; i++) {
        const int m = bm + ty * 8 + i;
        if (m >= M) continue;
#pragma unroll
        for (int j = 0; j < 8; j++) {
            const int n = bn + tx * 8 + j;
            if (n < N) {
                float v = acc[i][j];
                if (bias) v += bias[n];
                C[(size_t)m * N + n] = v;
            }
        }
    }
}

// ---------------- per-node attention scalars + init -------------------------
__global__ void node_att_kernel(const float* __restrict__ P,
                                const float* __restrict__ att_src,
                                const float* __restrict__ att_dst, int n_nodes)
{
    const int w = (blockIdx.x * blockDim.x + threadIdx.x) >> 5;
    const int lane = threadIdx.x & 31;
    if (w >= n_nodes * NHEAD) return;
    const int node = w / NHEAD;
    const int h = w - node * NHEAD;
    const float* row = P + (size_t)node * HC + h * CH;
    const float* as = att_src + h * CH;
    const float* ad = att_dst + h * CH;
    float s1 = 0.f, s2 = 0.f;
#pragma unroll
    for (int c = lane; c < CH; c += 32) {
        const float v = row[c];
        s1 += v * as[c];
        s2 += v * ad[c];
    }
#pragma unroll
    for (int o = 16; o > 0; o >>= 1) {
        s1 += __shfl_xor_sync(0xffffffffu, s1, o);
        s2 += __shfl_xor_sync(0xffffffffu, s2, o);
    }
    if (lane == 0) {
        g_asrc[w] = s1;
        g_adst[w] = s2;
        g_amax[w] = 0u;      // encodes below every finite float
        g_denom[w] = 0.f;
    }
}

// ---------------- CSR build --------------------------------------------------
__global__ void zero_counts_kernel(int n)
{
    const int i = blockIdx.x * blockDim.x + threadIdx.x;
    if (i < n) g_counts[i] = 0;
}

__global__ void hist_kernel(const void* __restrict__ ei, int E, int ET)
{
    const int e = blockIdx.x * blockDim.x + threadIdx.x;
    if (e >= ET) return;
    const int d = (e < E) ? load_idx(ei, (size_t)E + e) : (e - E);
    atomicAdd(&g_counts[d], 1);
}

__global__ void scan_kernel(int n)   // single block of 1024 threads
{
    __shared__ int warp_sums[32];
    __shared__ int s_carry;
    if (threadIdx.x == 0) s_carry = 0;
    __syncthreads();
    const int lane = threadIdx.x & 31;
    const int wid = threadIdx.x >> 5;
    for (int base = 0; base < n; base += 1024) {
        const int i = base + threadIdx.x;
        const int v = (i < n) ? g_counts[i] : 0;
        int x = v;
#pragma unroll
        for (int o = 1; o < 32; o <<= 1) {
            const int t = __shfl_up_sync(0xffffffffu, x, o);
            if (lane >= o) x += t;
        }
        if (lane == 31) warp_sums[wid] = x;
        __syncthreads();
        if (wid == 0) {
            int s = warp_sums[lane];
#pragma unroll
            for (int o = 1; o < 32; o <<= 1) {
                const int t = __shfl_up_sync(0xffffffffu, s, o);
                if (lane >= o) s += t;
            }
            warp_sums[lane] = s;
        }
        __syncthreads();
        const int incl = x + ((wid > 0) ? warp_sums[wid - 1] : 0) + s_carry;
        const int excl = incl - v;
        if (i < n) { g_rowoff[i] = excl; g_cursor[i] = excl; }
        __syncthreads();
        if (threadIdx.x == 1023) s_carry = incl;
        __syncthreads();
    }
    if (threadIdx.x == 0) g_rowoff[n] = s_carry;
}

__global__ void scatter_kernel(const void* __restrict__ ei, int E, int ET)
{
    const int e = blockIdx.x * blockDim.x + threadIdx.x;
    if (e >= ET) return;
    int s, d;
    if (e < E) { s = load_idx(ei, e); d = load_idx(ei, (size_t)E + e); }
    else       { s = d = e - E; }
    const int pos = atomicAdd(&g_cursor[d], 1);
    g_csr_e[pos] = e;
    g_csr_s[pos] = s;
}

// ---------------- edge passes -----------------------------------------------
__global__ void edge_pass1(const void* __restrict__ ei, int E, int ET)
{
    const int e = blockIdx.x * blockDim.x + threadIdx.x;
    if (e >= ET) return;
    int s, d;
    if (e < E) { s = load_idx(ei, e); d = load_idx(ei, (size_t)E + e); }
    else       { s = d = e - E; }
#pragma unroll
    for (int h = 0; h < NHEAD; h++) {
        float a = g_asrc[s * 3 + h] + g_adst[d * 3 + h];
        a = (a > 0.f) ? a : 0.2f * a;            // leaky relu, slope 0.2
        g_ex[(size_t)e * 3 + h] = a;
        atomicMax(&g_amax[d * 3 + h], f2enc(a));
    }
}

__global__ void edge_pass2(const void* __restrict__ ei, int E, int ET)
{
    const int e = blockIdx.x * blockDim.x + threadIdx.x;
    if (e >= ET) return;
    const int d = (e < E) ? load_idx(ei, (size_t)E + e) : (e - E);
#pragma unroll
    for (int h = 0; h < NHEAD; h++) {
        const float m = enc2f(g_amax[d * 3 + h]);
        const float ex = __expf(g_ex[(size_t)e * 3 + h] - m);
        g_ex[(size_t)e * 3 + h] = ex;
        atomicAdd(&g_denom[d * 3 + h], ex);
    }
}

// ---------------- CSR aggregation: out[d,:] = sum_e attn*P[src,:] + bias ----
__global__ __launch_bounds__(384) void gat_gather(
    const float* __restrict__ P, const float* __restrict__ bias,
    float* __restrict__ out, int n_nodes)
{
    const int j = threadIdx.x;       // 0..383
    const int h = j >> 7;            // head
    for (int d = blockIdx.x; d < n_nodes; d += gridDim.x) {
        const float inv = 1.f / (g_denom[d * 3 + h] + 1e-16f);
        float acc = bias[j];
        const int beg = g_rowoff[d];
        const int end = g_rowoff[d + 1];
        int i = beg;
        int e = 0, s = 0;
        if (i < end) { e = g_csr_e[i]; s = g_csr_s[i]; }
        while (i < end) {
            int e2 = 0, s2 = 0;
            if (i + 1 < end) { e2 = g_csr_e[i + 1]; s2 = g_csr_s[i + 1]; }  // prefetch
            const float attn = g_ex[(size_t)e * 3 + h] * inv;
            acc = fmaf(P[(size_t)s * HC + j], attn, acc);
            e = e2; s = s2; ++i;
        }
        out[(size_t)d * HC + j] = acc;
    }
}

// ---------------- launch -----------------------------------------------------
extern "C" void kernel_launch(void* const* d_in, const int* in_sizes, int n_in,
                              void* d_out, int out_size)
{
    const float* x    = (const float*)d_in[0];
    const void*  ei   = d_in[1];
    const float* W1   = (const float*)d_in[2];
    const float* as1  = (const float*)d_in[3];
    const float* ad1  = (const float*)d_in[4];
    const float* b1   = (const float*)d_in[5];
    const float* W2   = (const float*)d_in[6];
    const float* as2  = (const float*)d_in[7];
    const float* ad2  = (const float*)d_in[8];
    const float* b2   = (const float*)d_in[9];
    const float* outW = (const float*)d_in[10];
    const float* outb = (const float*)d_in[11];
    float* out = (float*)d_out;

    const int IN_DIM = 256, NCLS = 40;
    const int n_nodes = in_sizes[0] / IN_DIM;   // 50000
    const int E  = in_sizes[1] / 2;             // 800000
    const int ET = E + n_nodes;                 // 850000

    float *p, *agg;
    cudaGetSymbolAddress((void**)&p,   g_p);
    cudaGetSymbolAddress((void**)&agg, g_agg);

    const int TB = 256;
    const int eg = (ET + TB - 1) / TB;

    // dtype probe (must precede any edge read)
    detect_dtype_kernel<<<1, 256>>>((const int*)ei);

    // CSR by destination (shared by both layers)
    zero_counts_kernel<<<(n_nodes + TB - 1) / TB, TB>>>(n_nodes);
    hist_kernel<<<eg, TB>>>(ei, E, ET);
    scan_kernel<<<1, 1024>>>(n_nodes);
    scatter_kernel<<<eg, TB>>>(ei, E, ET);

    const dim3 g12((HC + 127) / 128, (n_nodes + 127) / 128);
    const int attg = (n_nodes * NHEAD * 32 + TB - 1) / TB;

    // ---- layer 1 ----
    sgemm_kernel<0><<<g12, 256>>>(x, W1, nullptr, p, n_nodes, HC, IN_DIM);
    node_att_kernel<<<attg, TB>>>(p, as1, ad1, n_nodes);
    edge_pass1<<<eg, TB>>>(ei, E, ET);
    edge_pass2<<<eg, TB>>>(ei, E, ET);
    gat_gather<<<n_nodes, 384>>>(p, b1, agg, n_nodes);

    // ---- layer 2 (relu fused into A-load of GEMM) ----
    sgemm_kernel<1><<<g12, 256>>>(agg, W2, nullptr, p, n_nodes, HC, HC);
    node_att_kernel<<<attg, TB>>>(p, as2, ad2, n_nodes);
    edge_pass1<<<eg, TB>>>(ei, E, ET);
    edge_pass2<<<eg, TB>>>(ei, E, ET);
    gat_gather<<<n_nodes, 384>>>(p, b2, agg, n_nodes);

    // ---- classifier head (relu fused into A-load) ----
    const dim3 g3((NCLS + 127) / 128, (n_nodes + 127) / 128);
    sgemm_kernel<1><<<g3, 256>>>(agg, outW, outb, out, n_nodes, NCLS, HC);
}

// round 3
// speedup vs baseline: 1.3113x; 1.3113x over previous
#include <cuda_runtime.h>
#include <math.h>

#define NMAX     50000
#define EMAX     850000
#define HC       384
#define CH       128
#define NHEAD    3

// ---------------- scratch (device globals; no allocation allowed) ----------
__device__ float    g_p[(size_t)NMAX * HC];     // projected features (per layer)
__device__ float    g_agg[(size_t)NMAX * HC];   // aggregated output (per layer)
__device__ float    g_asrc[NMAX * NHEAD];
__device__ float    g_adst[NMAX * NHEAD];
__device__ int      g_counts[NMAX];
__device__ int      g_rowoff[NMAX + 1];
__device__ int      g_cursor[NMAX];
__device__ int      g_csr_s[EMAX];
__device__ int      g_bsum[64];
__device__ int      g_boff[64];
__device__ int      g_is64;                     // 1 if edge_index is int64

// ---------------- helpers ---------------------------------------------------
__device__ __forceinline__ int load_idx(const void* ei, size_t i) {
    if (g_is64) return (int)((const long long*)ei)[i];
    return ((const int*)ei)[i];
}

// Detect edge_index dtype: view as int32; if int64 (LE, values < 2^31) every
// odd word is the zero high-half. 256 samples -> false positive prob ~0.
__global__ void detect_dtype_kernel(const int* __restrict__ ei32)
{
    __shared__ int any_nz;
    if (threadIdx.x == 0) any_nz = 0;
    __syncthreads();
    if (ei32[2 * threadIdx.x + 1] != 0) atomicOr(&any_nz, 1);
    __syncthreads();
    if (threadIdx.x == 0) g_is64 = any_nz ? 0 : 1;
}

// ---------------- SGEMM: C[M,N] = op(A)[M,K] @ B[K,N] (+bias) --------------
// 128x128 tile, BK=8, 256 threads, 8x8 microtile, register double buffering.
// ATT: fuse per-row attention dot products (per 128-col tile == one head).
template<int RELU_A, int ATT>
__global__ __launch_bounds__(256) void sgemm_kernel(
    const float* __restrict__ A, const float* __restrict__ B,
    const float* __restrict__ bias, float* __restrict__ C,
    const float* __restrict__ att_src, const float* __restrict__ att_dst,
    int M, int N, int K)
{
    __shared__ float As[2][8][128];
    __shared__ float Bs[2][8][128];
    const int tid = threadIdx.x;
    const int bm = blockIdx.y * 128;
    const int bn = blockIdx.x * 128;
    const int tx = tid & 15;
    const int ty = tid >> 4;
    const int arow = tid >> 1;
    const int acol = (tid & 1) << 2;
    const int brow = tid >> 5;
    const int bcol = (tid & 31) << 2;

    float acc[8][8];
#pragma unroll
    for (int i = 0; i < 8; i++)
#pragma unroll
        for (int j = 0; j < 8; j++) acc[i][j] = 0.f;

    const int gm = bm + arow;
    const bool avalid = (gm < M);
    const int gn = bn + bcol;

    // --- tile loaders (global -> registers) ---
    auto loadA = [&](int k0) -> float4 {
        float4 v = make_float4(0.f, 0.f, 0.f, 0.f);
        if (avalid)
            v = *reinterpret_cast<const float4*>(A + (size_t)gm * K + k0 + acol);
        if (RELU_A) {
            v.x = fmaxf(v.x, 0.f); v.y = fmaxf(v.y, 0.f);
            v.z = fmaxf(v.z, 0.f); v.w = fmaxf(v.w, 0.f);
        }
        return v;
    };
    auto loadB = [&](int k0) -> float4 {
        float4 v = make_float4(0.f, 0.f, 0.f, 0.f);
        const float* Brow = B + (size_t)(k0 + brow) * N;
        if (gn + 3 < N) {
            v = *reinterpret_cast<const float4*>(Brow + gn);
        } else {
            if (gn     < N) v.x = Brow[gn];
            if (gn + 1 < N) v.y = Brow[gn + 1];
            if (gn + 2 < N) v.z = Brow[gn + 2];
        }
        return v;
    };
    auto store = [&](int buf, float4 av, float4 bv) {
        As[buf][acol + 0][arow] = av.x;
        As[buf][acol + 1][arow] = av.y;
        As[buf][acol + 2][arow] = av.z;
        As[buf][acol + 3][arow] = av.w;
        *reinterpret_cast<float4*>(&Bs[buf][brow][bcol]) = bv;
    };
    auto compute = [&](int buf) {
#pragma unroll
        for (int k = 0; k < 8; k++) {
            float4 a0 = *reinterpret_cast<const float4*>(&As[buf][k][ty * 8]);
            float4 a1 = *reinterpret_cast<const float4*>(&As[buf][k][ty * 8 + 4]);
            float4 b0 = *reinterpret_cast<const float4*>(&Bs[buf][k][tx * 8]);
            float4 b1 = *reinterpret_cast<const float4*>(&Bs[buf][k][tx * 8 + 4]);
            float a[8] = {a0.x, a0.y, a0.z, a0.w, a1.x, a1.y, a1.z, a1.w};
            float b[8] = {b0.x, b0.y, b0.z, b0.w, b1.x, b1.y, b1.z, b1.w};
#pragma unroll
            for (int i = 0; i < 8; i++)
#pragma unroll
                for (int j = 0; j < 8; j++)
                    acc[i][j] = fmaf(a[i], b[j], acc[i][j]);
        }
    };

    // --- pipelined mainloop ---
    {
        float4 av = loadA(0), bv = loadB(0);
        store(0, av, bv);
    }
    __syncthreads();
    int cur = 0;
    for (int k0 = 8; k0 < K; k0 += 8) {
        float4 av = loadA(k0), bv = loadB(k0);   // LDG in flight during compute
        compute(cur);
        store(cur ^ 1, av, bv);
        __syncthreads();
        cur ^= 1;
    }
    compute(cur);

    // --- epilogue: C store (+bias) ---
#pragma unroll
    for (int i = 0; i < 8; i++) {
        const int m = bm + ty * 8 + i;
        if (m >= M) continue;
#pragma unroll
        for (int j = 0; j < 8; j++) {
            const int n = bn + tx * 8 + j;
            if (n < N) {
                float v = acc[i][j];
                if (bias) v += bias[n];
                C[(size_t)m * N + n] = v;
            }
        }
    }

    // --- fused attention dots: a_src/a_dst per (row, head) ---
    if (ATT) {
        const int head = bn >> 7;                 // N=384, 128-col tile == head
        float as_v[8], ad_v[8];
#pragma unroll
        for (int j = 0; j < 8; j++) {
            as_v[j] = att_src[head * CH + tx * 8 + j];
            ad_v[j] = att_dst[head * CH + tx * 8 + j];
        }
#pragma unroll
        for (int i = 0; i < 8; i++) {
            float s1 = 0.f, s2 = 0.f;
#pragma unroll
            for (int j = 0; j < 8; j++) {
                s1 = fmaf(acc[i][j], as_v[j], s1);
                s2 = fmaf(acc[i][j], ad_v[j], s2);
            }
#pragma unroll
            for (int o = 8; o >= 1; o >>= 1) {    // reduce over 16 tx lanes
                s1 += __shfl_xor_sync(0xffffffffu, s1, o);
                s2 += __shfl_xor_sync(0xffffffffu, s2, o);
            }
            const int m = bm + ty * 8 + i;
            if (tx == 0 && m < M) {
                g_asrc[m * 3 + head] = s1;
                g_adst[m * 3 + head] = s2;
            }
        }
    }
}

// ---------------- CSR build --------------------------------------------------
__global__ void zero_counts_kernel(int n)
{
    const int i = blockIdx.x * blockDim.x + threadIdx.x;
    if (i < n) g_counts[i] = 0;
}

__global__ void hist_kernel(const void* __restrict__ ei, int E, int ET)
{
    const int e = blockIdx.x * blockDim.x + threadIdx.x;
    if (e >= ET) return;
    const int d = (e < E) ? load_idx(ei, (size_t)E + e) : (e - E);
    atomicAdd(&g_counts[d], 1);
}

// block-local exclusive scan (1024/block) + block sums
__global__ __launch_bounds__(1024) void scan1_kernel(int n)
{
    __shared__ int wsum[32];
    const int i = blockIdx.x * 1024 + threadIdx.x;
    const int lane = threadIdx.x & 31;
    const int wid = threadIdx.x >> 5;
    const int v = (i < n) ? g_counts[i] : 0;
    int x = v;
#pragma unroll
    for (int o = 1; o < 32; o <<= 1) {
        const int t = __shfl_up_sync(0xffffffffu, x, o);
        if (lane >= o) x += t;
    }
    if (lane == 31) wsum[wid] = x;
    __syncthreads();
    if (wid == 0) {
        int s = wsum[lane];
#pragma unroll
        for (int o = 1; o < 32; o <<= 1) {
            const int t = __shfl_up_sync(0xffffffffu, s, o);
            if (lane >= o) s += t;
        }
        wsum[lane] = s;
    }
    __syncthreads();
    const int incl = x + ((wid > 0) ? wsum[wid - 1] : 0);
    if (i < n) g_rowoff[i] = incl - v;
    if (threadIdx.x == 1023) g_bsum[blockIdx.x] = incl;
}

// scan of <=64 block sums (1 warp)
__global__ void scan2_kernel(int nb, int n)
{
    const int lane = threadIdx.x;
    const int a = (lane < nb) ? g_bsum[lane] : 0;
    const int b = (32 + lane < nb) ? g_bsum[32 + lane] : 0;
    int xa = a, xb = b;
#pragma unroll
    for (int o = 1; o < 32; o <<= 1) {
        int t = __shfl_up_sync(0xffffffffu, xa, o);
        if (lane >= o) xa += t;
        t = __shfl_up_sync(0xffffffffu, xb, o);
        if (lane >= o) xb += t;
    }
    const int totA = __shfl_sync(0xffffffffu, xa, 31);
    const int totB = __shfl_sync(0xffffffffu, xb, 31);
    g_boff[lane] = xa - a;
    g_boff[32 + lane] = totA + xb - b;
    if (lane == 31) g_rowoff[n] = totA + totB;
}

__global__ void scan3_kernel(int n)
{
    const int i = blockIdx.x * blockDim.x + threadIdx.x;
    if (i >= n) return;
    const int off = g_rowoff[i] + g_boff[i >> 10];
    g_rowoff[i] = off;
    g_cursor[i] = off;
}

__global__ void scatter_kernel(const void* __restrict__ ei, int E, int ET)
{
    const int e = blockIdx.x * blockDim.x + threadIdx.x;
    if (e >= ET) return;
    int s, d;
    if (e < E) { s = load_idx(ei, e); d = load_idx(ei, (size_t)E + e); }
    else       { s = d = e - E; }
    const int pos = atomicAdd(&g_cursor[d], 1);
    g_csr_s[pos] = s;
}

// ---------------- fused softmax + aggregation per dst node ------------------
// out[d,:] = sum_e softmax(lrelu(asrc[s]+adst[d]))*P[s,:] + bias
__global__ __launch_bounds__(384) void gat_gather(
    const float* __restrict__ P, const float* __restrict__ bias,
    float* __restrict__ out, int n_nodes)
{
    __shared__ int   s_sh[384];
    __shared__ float al_sh[3][384];           // alpha, then exp weights
    __shared__ float sm_m[3], sm_sum[3], sm_scale[3], sm_adst[3];
    const int j = threadIdx.x;                // channel 0..383
    const int h = j >> 7;                     // head
    const int wid = j >> 5;
    const int lane = j & 31;
    const float bj = bias[j];

    for (int d = blockIdx.x; d < n_nodes; d += gridDim.x) {
        const int beg = g_rowoff[d];
        const int end = g_rowoff[d + 1];
        if (j < 3) {
            sm_m[j] = -INFINITY;
            sm_sum[j] = 0.f;
            sm_adst[j] = g_adst[d * 3 + j];
        }
        __syncthreads();
        float acc = 0.f;

        for (int base = beg; base < end; base += 384) {
            const int cnt = min(384, end - base);
            if (j < cnt) {
                const int s = g_csr_s[base + j];
                s_sh[j] = s;
#pragma unroll
                for (int hh = 0; hh < 3; hh++) {
                    float a = g_asrc[s * 3 + hh] + sm_adst[hh];
                    al_sh[hh][j] = (a > 0.f) ? a : 0.2f * a;   // leaky relu
                }
            }
            __syncthreads();
            if (wid < 3) {                    // warp `wid` owns head `wid`
                float mx = -INFINITY;
                for (int i = lane; i < cnt; i += 32)
                    mx = fmaxf(mx, al_sh[wid][i]);
#pragma unroll
                for (int o = 16; o; o >>= 1)
                    mx = fmaxf(mx, __shfl_xor_sync(0xffffffffu, mx, o));
                const float oldm = sm_m[wid];
                const float newm = fmaxf(oldm, mx);
                float sum = 0.f;
                for (int i = lane; i < cnt; i += 32) {
                    const float w = __expf(al_sh[wid][i] - newm);
                    al_sh[wid][i] = w;
                    sum += w;
                }
#pragma unroll
                for (int o = 16; o; o >>= 1)
                    sum += __shfl_xor_sync(0xffffffffu, sum, o);
                if (lane == 0) {
                    const float sc = __expf(oldm - newm);   // 0 on first chunk
                    sm_scale[wid] = sc;
                    sm_sum[wid] = sm_sum[wid] * sc + sum;
                    sm_m[wid] = newm;
                }
            }
            __syncthreads();
            acc *= sm_scale[h];
#pragma unroll 4
            for (int i = 0; i < cnt; i++)
                acc = fmaf(al_sh[h][i], P[(size_t)s_sh[i] * HC + j], acc);
            __syncthreads();                  // smem reused next chunk
        }
        out[(size_t)d * HC + j] = acc / (sm_sum[h] + 1e-16f) + bj;
        __syncthreads();                      // before sm_* reset next iter
    }
}

// ---------------- launch -----------------------------------------------------
extern "C" void kernel_launch(void* const* d_in, const int* in_sizes, int n_in,
                              void* d_out, int out_size)
{
    const float* x    = (const float*)d_in[0];
    const void*  ei   = d_in[1];
    const float* W1   = (const float*)d_in[2];
    const float* as1  = (const float*)d_in[3];
    const float* ad1  = (const float*)d_in[4];
    const float* b1   = (const float*)d_in[5];
    const float* W2   = (const float*)d_in[6];
    const float* as2  = (const float*)d_in[7];
    const float* ad2  = (const float*)d_in[8];
    const float* b2   = (const float*)d_in[9];
    const float* outW = (const float*)d_in[10];
    const float* outb = (const float*)d_in[11];
    float* out = (float*)d_out;

    const int IN_DIM = 256, NCLS = 40;
    const int n_nodes = in_sizes[0] / IN_DIM;   // 50000
    const int E  = in_sizes[1] / 2;             // 800000
    const int ET = E + n_nodes;                 // 850000

    float *p, *agg;
    cudaGetSymbolAddress((void**)&p,   g_p);
    cudaGetSymbolAddress((void**)&agg, g_agg);

    const int TB = 256;
    const int eg = (ET + TB - 1) / TB;
    const int nb = (n_nodes + 1023) / 1024;

    // dtype probe (must precede any edge read)
    detect_dtype_kernel<<<1, 256>>>((const int*)ei);

    // CSR by destination (shared by both layers)
    zero_counts_kernel<<<(n_nodes + TB - 1) / TB, TB>>>(n_nodes);
    hist_kernel<<<eg, TB>>>(ei, E, ET);
    scan1_kernel<<<nb, 1024>>>(n_nodes);
    scan2_kernel<<<1, 32>>>(nb, n_nodes);
    scan3_kernel<<<(n_nodes + TB - 1) / TB, TB>>>(n_nodes);
    scatter_kernel<<<eg, TB>>>(ei, E, ET);

    const dim3 g12((HC + 127) / 128, (n_nodes + 127) / 128);
    const dim3 g3((NCLS + 127) / 128, (n_nodes + 127) / 128);

    // ---- layer 1 ----
    sgemm_kernel<0, 1><<<g12, 256>>>(x, W1, nullptr, p, as1, ad1, n_nodes, HC, IN_DIM);
    gat_gather<<<n_nodes, 384>>>(p, b1, agg, n_nodes);

    // ---- layer 2 (relu fused into A-load of GEMM) ----
    sgemm_kernel<1, 1><<<g12, 256>>>(agg, W2, nullptr, p, as2, ad2, n_nodes, HC, HC);
    gat_gather<<<n_nodes, 384>>>(p, b2, agg, n_nodes);

    // ---- classifier head (relu fused into A-load) ----
    sgemm_kernel<1, 0><<<g3, 256>>>(agg, outW, outb, out, nullptr, nullptr,
                                    n_nodes, NCLS, HC);
}

// round 4
// speedup vs baseline: 1.4345x; 1.0939x over previous
#include <cuda_runtime.h>
#include <math.h>

#define NMAX     50000
#define EMAX     850000
#define HC       384
#define CH       128
#define NHEAD    3

// ---------------- scratch (device globals; no allocation allowed) ----------
__device__ float    g_p[(size_t)NMAX * HC];     // projected features (per layer)
__device__ float    g_agg[(size_t)NMAX * HC];   // aggregated output (per layer)
__device__ float    g_asrc[NMAX * NHEAD];
__device__ float    g_adst[NMAX * NHEAD];
__device__ int      g_counts[NMAX];
__device__ int      g_rowoff[NMAX + 1];
__device__ int      g_cursor[NMAX];
__device__ int      g_csr_s[EMAX];
__device__ int      g_bsum[64];
__device__ int      g_boff[64];
__device__ int      g_is64;                     // 1 if edge_index is int64

// ---------------- helpers ---------------------------------------------------
__device__ __forceinline__ int load_idx(const void* ei, size_t i) {
    if (g_is64) return (int)((const long long*)ei)[i];
    return ((const int*)ei)[i];
}

__device__ __forceinline__ unsigned long long pk2(float lo, float hi) {
    unsigned long long r;
    asm("mov.b64 %0, {%1, %2};" : "=l"(r) : "f"(lo), "f"(hi));
    return r;
}
__device__ __forceinline__ void ffma2(unsigned long long& d,
                                      unsigned long long a, unsigned long long b) {
    asm("fma.rn.f32x2 %0, %1, %2, %0;" : "+l"(d) : "l"(a), "l"(b));
}
__device__ __forceinline__ void unpk2(unsigned long long v, float& lo, float& hi) {
    asm("mov.b64 {%0, %1}, %2;" : "=f"(lo), "=f"(hi) : "l"(v));
}

// Detect edge_index dtype: view as int32; if int64 (LE, values < 2^31) every
// odd word is the zero high-half. 256 samples -> false positive prob ~0.
__global__ void detect_dtype_kernel(const int* __restrict__ ei32)
{
    __shared__ int any_nz;
    if (threadIdx.x == 0) any_nz = 0;
    __syncthreads();
    if (ei32[2 * threadIdx.x + 1] != 0) atomicOr(&any_nz, 1);
    __syncthreads();
    if (threadIdx.x == 0) g_is64 = any_nz ? 0 : 1;
}

// ---------------- SGEMM: C[M,N] = op(A)[M,K] @ B[K,N] (+bias) --------------
// 128x128 tile, BK=8, 256 threads, 8x8 microtile via packed f32x2 FFMA2,
// register double buffering. ATT: fuse attention dots (128-col tile == head).
template<int RELU_A, int ATT>
__global__ __launch_bounds__(256) void sgemm_kernel(
    const float* __restrict__ A, const float* __restrict__ B,
    const float* __restrict__ bias, float* __restrict__ C,
    const float* __restrict__ att_src, const float* __restrict__ att_dst,
    int M, int N, int K)
{
    __shared__ float As[2][8][128];
    __shared__ float Bs[2][8][128];
    const int tid = threadIdx.x;
    const int bm = blockIdx.y * 128;
    const int bn = blockIdx.x * 128;
    const int tx = tid & 15;
    const int ty = tid >> 4;
    const int arow = tid >> 1;
    const int acol = (tid & 1) << 2;
    const int brow = tid >> 5;
    const int bcol = (tid & 31) << 2;

    unsigned long long acc2[8][4];      // [i][jp]: cols (jp*2, jp*2+1)
#pragma unroll
    for (int i = 0; i < 8; i++)
#pragma unroll
        for (int jp = 0; jp < 4; jp++) acc2[i][jp] = 0ull;

    const int gm = bm + arow;
    const bool avalid = (gm < M);
    const int gn = bn + bcol;

    auto loadA = [&](int k0) -> float4 {
        float4 v = make_float4(0.f, 0.f, 0.f, 0.f);
        if (avalid)
            v = *reinterpret_cast<const float4*>(A + (size_t)gm * K + k0 + acol);
        if (RELU_A) {
            v.x = fmaxf(v.x, 0.f); v.y = fmaxf(v.y, 0.f);
            v.z = fmaxf(v.z, 0.f); v.w = fmaxf(v.w, 0.f);
        }
        return v;
    };
    auto loadB = [&](int k0) -> float4 {
        float4 v = make_float4(0.f, 0.f, 0.f, 0.f);
        const float* Brow = B + (size_t)(k0 + brow) * N;
        if (gn + 3 < N) {
            v = *reinterpret_cast<const float4*>(Brow + gn);
        } else {
            if (gn     < N) v.x = Brow[gn];
            if (gn + 1 < N) v.y = Brow[gn + 1];
            if (gn + 2 < N) v.z = Brow[gn + 2];
        }
        return v;
    };
    auto store = [&](int buf, float4 av, float4 bv) {
        As[buf][acol + 0][arow] = av.x;
        As[buf][acol + 1][arow] = av.y;
        As[buf][acol + 2][arow] = av.z;
        As[buf][acol + 3][arow] = av.w;
        *reinterpret_cast<float4*>(&Bs[buf][brow][bcol]) = bv;
    };
    auto compute = [&](int buf) {
#pragma unroll
        for (int k = 0; k < 8; k++) {
            float4 a0 = *reinterpret_cast<const float4*>(&As[buf][k][ty * 8]);
            float4 a1 = *reinterpret_cast<const float4*>(&As[buf][k][ty * 8 + 4]);
            float4 b0 = *reinterpret_cast<const float4*>(&Bs[buf][k][tx * 8]);
            float4 b1 = *reinterpret_cast<const float4*>(&Bs[buf][k][tx * 8 + 4]);
            unsigned long long bp[4] = {
                pk2(b0.x, b0.y), pk2(b0.z, b0.w),
                pk2(b1.x, b1.y), pk2(b1.z, b1.w)
            };
            float a[8] = {a0.x, a0.y, a0.z, a0.w, a1.x, a1.y, a1.z, a1.w};
#pragma unroll
            for (int i = 0; i < 8; i++) {
                const unsigned long long ap = pk2(a[i], a[i]);
#pragma unroll
                for (int jp = 0; jp < 4; jp++)
                    ffma2(acc2[i][jp], ap, bp[jp]);
            }
        }
    };

    // --- pipelined mainloop ---
    {
        float4 av = loadA(0), bv = loadB(0);
        store(0, av, bv);
    }
    __syncthreads();
    int cur = 0;
    for (int k0 = 8; k0 < K; k0 += 8) {
        float4 av = loadA(k0), bv = loadB(k0);   // LDG in flight during compute
        compute(cur);
        store(cur ^ 1, av, bv);
        __syncthreads();
        cur ^= 1;
    }
    compute(cur);

    // --- unpack accumulators ---
    float acc[8][8];
#pragma unroll
    for (int i = 0; i < 8; i++)
#pragma unroll
        for (int jp = 0; jp < 4; jp++)
            unpk2(acc2[i][jp], acc[i][jp * 2], acc[i][jp * 2 + 1]);

    // --- epilogue: C store (+bias) ---
#pragma unroll
    for (int i = 0; i < 8; i++) {
        const int m = bm + ty * 8 + i;
        if (m >= M) continue;
#pragma unroll
        for (int j = 0; j < 8; j++) {
            const int n = bn + tx * 8 + j;
            if (n < N) {
                float v = acc[i][j];
                if (bias) v += bias[n];
                C[(size_t)m * N + n] = v;
            }
        }
    }

    // --- fused attention dots: a_src/a_dst per (row, head) ---
    if (ATT) {
        const int head = bn >> 7;                 // N=384, 128-col tile == head
        float as_v[8], ad_v[8];
#pragma unroll
        for (int j = 0; j < 8; j++) {
            as_v[j] = att_src[head * CH + tx * 8 + j];
            ad_v[j] = att_dst[head * CH + tx * 8 + j];
        }
#pragma unroll
        for (int i = 0; i < 8; i++) {
            float s1 = 0.f, s2 = 0.f;
#pragma unroll
            for (int j = 0; j < 8; j++) {
                s1 = fmaf(acc[i][j], as_v[j], s1);
                s2 = fmaf(acc[i][j], ad_v[j], s2);
            }
#pragma unroll
            for (int o = 8; o >= 1; o >>= 1) {    // reduce over 16 tx lanes
                s1 += __shfl_xor_sync(0xffffffffu, s1, o);
                s2 += __shfl_xor_sync(0xffffffffu, s2, o);
            }
            const int m = bm + ty * 8 + i;
            if (tx == 0 && m < M) {
                g_asrc[m * 3 + head] = s1;
                g_adst[m * 3 + head] = s2;
            }
        }
    }
}

// ---------------- head GEMM: C[M,40] = relu(A)[M,384] @ B[384,40] + bias ----
// 128-row tile, 256 threads, per-thread 4 rows x 5 cols. No wasted FMAs.
__global__ __launch_bounds__(256) void sgemm_head_kernel(
    const float* __restrict__ A, const float* __restrict__ B,
    const float* __restrict__ bias, float* __restrict__ C, int M)
{
    const int NK = 384, NN = 40;
    __shared__ float As[8][128];
    __shared__ float Bs[8][40];
    const int tid = threadIdx.x;
    const int bm = blockIdx.x * 128;
    const int tx = tid & 7;          // col group: cols tx*5 .. tx*5+4
    const int ty = tid >> 3;         // row group: rows ty*4 .. ty*4+3
    const int arow = tid >> 1;
    const int acol = (tid & 1) << 2;
    const int gm = bm + arow;
    const bool avalid = (gm < M);

    float acc[4][5];
#pragma unroll
    for (int i = 0; i < 4; i++)
#pragma unroll
        for (int j = 0; j < 5; j++) acc[i][j] = 0.f;

    for (int k0 = 0; k0 < NK; k0 += 8) {
        float4 av = make_float4(0.f, 0.f, 0.f, 0.f);
        if (avalid)
            av = *reinterpret_cast<const float4*>(A + (size_t)gm * NK + k0 + acol);
        As[acol + 0][arow] = fmaxf(av.x, 0.f);
        As[acol + 1][arow] = fmaxf(av.y, 0.f);
        As[acol + 2][arow] = fmaxf(av.z, 0.f);
        As[acol + 3][arow] = fmaxf(av.w, 0.f);
        if (tid < 160) {             // 8*40 = 320 values, 2 per thread
            const int r0 = tid / 20, c0 = (tid % 20) * 2;
            Bs[r0][c0]     = B[(size_t)(k0 + r0) * NN + c0];
            Bs[r0][c0 + 1] = B[(size_t)(k0 + r0) * NN + c0 + 1];
        }
        __syncthreads();
#pragma unroll
        for (int k = 0; k < 8; k++) {
            float a[4], b[5];
#pragma unroll
            for (int i = 0; i < 4; i++) a[i] = As[k][ty * 4 + i];
#pragma unroll
            for (int j = 0; j < 5; j++) b[j] = Bs[k][tx * 5 + j];
#pragma unroll
            for (int i = 0; i < 4; i++)
#pragma unroll
                for (int j = 0; j < 5; j++)
                    acc[i][j] = fmaf(a[i], b[j], acc[i][j]);
        }
        __syncthreads();
    }
#pragma unroll
    for (int i = 0; i < 4; i++) {
        const int m = bm + ty * 4 + i;
        if (m >= M) continue;
#pragma unroll
        for (int j = 0; j < 5; j++) {
            const int n = tx * 5 + j;
            C[(size_t)m * NN + n] = acc[i][j] + bias[n];
        }
    }
}

// ---------------- CSR build --------------------------------------------------
__global__ void zero_counts_kernel(int n)
{
    const int i = blockIdx.x * blockDim.x + threadIdx.x;
    if (i < n) g_counts[i] = 0;
}

__global__ void hist_kernel(const void* __restrict__ ei, int E, int ET)
{
    const int e = blockIdx.x * blockDim.x + threadIdx.x;
    if (e >= ET) return;
    const int d = (e < E) ? load_idx(ei, (size_t)E + e) : (e - E);
    atomicAdd(&g_counts[d], 1);
}

// block-local exclusive scan (1024/block) + block sums
__global__ __launch_bounds__(1024) void scan1_kernel(int n)
{
    __shared__ int wsum[32];
    const int i = blockIdx.x * 1024 + threadIdx.x;
    const int lane = threadIdx.x & 31;
    const int wid = threadIdx.x >> 5;
    const int v = (i < n) ? g_counts[i] : 0;
    int x = v;
#pragma unroll
    for (int o = 1; o < 32; o <<= 1) {
        const int t = __shfl_up_sync(0xffffffffu, x, o);
        if (lane >= o) x += t;
    }
    if (lane == 31) wsum[wid] = x;
    __syncthreads();
    if (wid == 0) {
        int s = wsum[lane];
#pragma unroll
        for (int o = 1; o < 32; o <<= 1) {
            const int t = __shfl_up_sync(0xffffffffu, s, o);
            if (lane >= o) s += t;
        }
        wsum[lane] = s;
    }
    __syncthreads();
    const int incl = x + ((wid > 0) ? wsum[wid - 1] : 0);
    if (i < n) g_rowoff[i] = incl - v;
    if (threadIdx.x == 1023) g_bsum[blockIdx.x] = incl;
}

// scan of <=64 block sums (1 warp)
__global__ void scan2_kernel(int nb, int n)
{
    const int lane = threadIdx.x;
    const int a = (lane < nb) ? g_bsum[lane] : 0;
    const int b = (32 + lane < nb) ? g_bsum[32 + lane] : 0;
    int xa = a, xb = b;
#pragma unroll
    for (int o = 1; o < 32; o <<= 1) {
        int t = __shfl_up_sync(0xffffffffu, xa, o);
        if (lane >= o) xa += t;
        t = __shfl_up_sync(0xffffffffu, xb, o);
        if (lane >= o) xb += t;
    }
    const int totA = __shfl_sync(0xffffffffu, xa, 31);
    const int totB = __shfl_sync(0xffffffffu, xb, 31);
    g_boff[lane] = xa - a;
    g_boff[32 + lane] = totA + xb - b;
    if (lane == 31) g_rowoff[n] = totA + totB;
}

__global__ void scan3_kernel(int n)
{
    const int i = blockIdx.x * blockDim.x + threadIdx.x;
    if (i >= n) return;
    const int off = g_rowoff[i] + g_boff[i >> 10];
    g_rowoff[i] = off;
    g_cursor[i] = off;
}

__global__ void scatter_kernel(const void* __restrict__ ei, int E, int ET)
{
    const int e = blockIdx.x * blockDim.x + threadIdx.x;
    if (e >= ET) return;
    int s, d;
    if (e < E) { s = load_idx(ei, e); d = load_idx(ei, (size_t)E + e); }
    else       { s = d = e - E; }
    const int pos = atomicAdd(&g_cursor[d], 1);
    g_csr_s[pos] = s;
}

// ---------------- fused softmax + aggregation per dst node ------------------
// out[d,:] = sum_e softmax(lrelu(asrc[s]+adst[d]))*P[s,:] + bias
__global__ __launch_bounds__(384) void gat_gather(
    const float* __restrict__ P, const float* __restrict__ bias,
    float* __restrict__ out, int n_nodes)
{
    __shared__ int   s_sh[384];
    __shared__ float al_sh[3][384];           // alpha, then exp weights
    __shared__ float sm_m[3], sm_sum[3], sm_scale[3], sm_adst[3];
    const int j = threadIdx.x;                // channel 0..383
    const int h = j >> 7;                     // head
    const int wid = j >> 5;
    const int lane = j & 31;
    const float bj = bias[j];

    for (int d = blockIdx.x; d < n_nodes; d += gridDim.x) {
        const int beg = g_rowoff[d];
        const int end = g_rowoff[d + 1];
        if (j < 3) {
            sm_m[j] = -INFINITY;
            sm_sum[j] = 0.f;
            sm_adst[j] = g_adst[d * 3 + j];
        }
        __syncthreads();
        float acc = 0.f;

        for (int base = beg; base < end; base += 384) {
            const int cnt = min(384, end - base);
            if (j < cnt) {
                const int s = g_csr_s[base + j];
                s_sh[j] = s;
#pragma unroll
                for (int hh = 0; hh < 3; hh++) {
                    float a = g_asrc[s * 3 + hh] + sm_adst[hh];
                    al_sh[hh][j] = (a > 0.f) ? a : 0.2f * a;   // leaky relu
                }
            }
            __syncthreads();
            if (wid < 3) {                    // warp `wid` owns head `wid`
                float mx = -INFINITY;
                for (int i = lane; i < cnt; i += 32)
                    mx = fmaxf(mx, al_sh[wid][i]);
#pragma unroll
                for (int o = 16; o; o >>= 1)
                    mx = fmaxf(mx, __shfl_xor_sync(0xffffffffu, mx, o));
                const float oldm = sm_m[wid];
                const float newm = fmaxf(oldm, mx);
                float sum = 0.f;
                for (int i = lane; i < cnt; i += 32) {
                    const float w = __expf(al_sh[wid][i] - newm);
                    al_sh[wid][i] = w;
                    sum += w;
                }
#pragma unroll
                for (int o = 16; o; o >>= 1)
                    sum += __shfl_xor_sync(0xffffffffu, sum, o);
                if (lane == 0) {
                    const float sc = __expf(oldm - newm);   // 0 on first chunk
                    sm_scale[wid] = sc;
                    sm_sum[wid] = sm_sum[wid] * sc + sum;
                    sm_m[wid] = newm;
                }
            }
            __syncthreads();
            acc *= sm_scale[h];
#pragma unroll 4
            for (int i = 0; i < cnt; i++)
                acc = fmaf(al_sh[h][i], P[(size_t)s_sh[i] * HC + j], acc);
            __syncthreads();                  // smem reused next chunk
        }
        out[(size_t)d * HC + j] = acc / (sm_sum[h] + 1e-16f) + bj;
        __syncthreads();                      // before sm_* reset next iter
    }
}

// ---------------- launch -----------------------------------------------------
extern "C" void kernel_launch(void* const* d_in, const int* in_sizes, int n_in,
                              void* d_out, int out_size)
{
    const float* x    = (const float*)d_in[0];
    const void*  ei   = d_in[1];
    const float* W1   = (const float*)d_in[2];
    const float* as1  = (const float*)d_in[3];
    const float* ad1  = (const float*)d_in[4];
    const float* b1   = (const float*)d_in[5];
    const float* W2   = (const float*)d_in[6];
    const float* as2  = (const float*)d_in[7];
    const float* ad2  = (const float*)d_in[8];
    const float* b2   = (const float*)d_in[9];
    const float* outW = (const float*)d_in[10];
    const float* outb = (const float*)d_in[11];
    float* out = (float*)d_out;

    const int IN_DIM = 256;
    const int n_nodes = in_sizes[0] / IN_DIM;   // 50000
    const int E  = in_sizes[1] / 2;             // 800000
    const int ET = E + n_nodes;                 // 850000

    float *p, *agg;
    cudaGetSymbolAddress((void**)&p,   g_p);
    cudaGetSymbolAddress((void**)&agg, g_agg);

    const int TB = 256;
    const int eg = (ET + TB - 1) / TB;
    const int nb = (n_nodes + 1023) / 1024;

    // dtype probe (must precede any edge read)
    detect_dtype_kernel<<<1, 256>>>((const int*)ei);

    // CSR by destination (shared by both layers)
    zero_counts_kernel<<<(n_nodes + TB - 1) / TB, TB>>>(n_nodes);
    hist_kernel<<<eg, TB>>>(ei, E, ET);
    scan1_kernel<<<nb, 1024>>>(n_nodes);
    scan2_kernel<<<1, 32>>>(nb, n_nodes);
    scan3_kernel<<<(n_nodes + TB - 1) / TB, TB>>>(n_nodes);
    scatter_kernel<<<eg, TB>>>(ei, E, ET);

    const dim3 g12((HC + 127) / 128, (n_nodes + 127) / 128);

    // ---- layer 1 ----
    sgemm_kernel<0, 1><<<g12, 256>>>(x, W1, nullptr, p, as1, ad1, n_nodes, HC, IN_DIM);
    gat_gather<<<n_nodes, 384>>>(p, b1, agg, n_nodes);

    // ---- layer 2 (relu fused into A-load of GEMM) ----
    sgemm_kernel<1, 1><<<g12, 256>>>(agg, W2, nullptr, p, as2, ad2, n_nodes, HC, HC);
    gat_gather<<<n_nodes, 384>>>(p, b2, agg, n_nodes);

    // ---- classifier head (relu fused into A-load) ----
    sgemm_head_kernel<<<(n_nodes + 127) / 128, 256>>>(agg, outW, outb, out, n_nodes);
}